// round 2
// baseline (speedup 1.0000x reference)
#include <cuda_runtime.h>
#include <cuda_bf16.h>

#define Nn 100000
#define Ee 1600000
#define Dd 32
#define ET (Ee + Nn)   // edges + self loops

// Scratch (device globals: no allocation allowed in kernel_launch).
// 16B alignment is REQUIRED for the float4 loads / red.global.add.v4.f32.
__device__ __align__(16) float g_h[Nn * Dd];     // transformed features h = in @ W
__device__ __align__(16) float g_acc[Nn * Dd];   // output accumulator
__device__ float g_as[Nn];                       // alpha_src per node
__device__ float g_ad[Nn];                       // alpha_dst per node
__device__ float g_s[Nn];                        // softmax denominator per dst
__device__ float g_w[ET];                        // exp(leaky(alpha)) per edge

// ---------------------------------------------------------------------------
// K1: h = in @ W  (N x 32 @ 32 x 32), alpha_src/alpha_dst dot products,
//     and zero the per-layer accumulators. One warp per row.
// ---------------------------------------------------------------------------
__global__ void k_gemm_alpha(const float* __restrict__ in,
                             const float* __restrict__ W,
                             const float* __restrict__ a_s,
                             const float* __restrict__ a_d) {
    __shared__ float Ws[Dd * Dd];
    __shared__ float asv[Dd];
    __shared__ float adv[Dd];
    int tid = threadIdx.x;
    for (int i = tid; i < Dd * Dd; i += blockDim.x) Ws[i] = W[i];
    if (tid < Dd) { asv[tid] = a_s[tid]; adv[tid] = a_d[tid]; }
    __syncthreads();

    int warp = tid >> 5;
    int lane = tid & 31;
    int row = blockIdx.x * (blockDim.x >> 5) + warp;
    if (row >= Nn) return;

    float xr = in[row * Dd + lane];
    float h = 0.f;
#pragma unroll
    for (int k = 0; k < Dd; k++)
        h = fmaf(__shfl_sync(0xffffffffu, xr, k), Ws[k * Dd + lane], h);

    g_h[row * Dd + lane]   = h;
    g_acc[row * Dd + lane] = 0.f;

    float vs = h * asv[lane];
    float vd = h * adv[lane];
#pragma unroll
    for (int o = 16; o > 0; o >>= 1) {
        vs += __shfl_xor_sync(0xffffffffu, vs, o);
        vd += __shfl_xor_sync(0xffffffffu, vd, o);
    }
    if (lane == 0) {
        g_as[row] = vs;
        g_ad[row] = vd;
        g_s[row]  = 0.f;
    }
}

// ---------------------------------------------------------------------------
// K2: per-edge attention weight w = exp(leakyrelu(as[src] + ad[dst])),
//     accumulate softmax denominator s[dst].
//     Max-subtraction omitted: alpha is O(10) bounded, exp cannot overflow,
//     and softmax is shift-invariant so the result is identical.
// ---------------------------------------------------------------------------
__global__ void k_edge_w(const int* __restrict__ src,
                         const int* __restrict__ dst) {
    int e = blockIdx.x * blockDim.x + threadIdx.x;
    if (e >= ET) return;
    int s, d;
    if (e < Ee) { s = __ldg(src + e); d = __ldg(dst + e); }
    else        { s = d = e - Ee; }        // self loop
    float a = g_as[s] + g_ad[d];
    a = a > 0.f ? a : 0.2f * a;            // leaky_relu(0.2)
    float w = __expf(a);
    g_w[e] = w;
    atomicAdd(&g_s[d], w);
}

// ---------------------------------------------------------------------------
// K3: aggregation: acc[dst] += h[src] * (w / s[dst]).
//     8 threads per edge, float4 gather + red.global.add.v4.f32 scatter.
// ---------------------------------------------------------------------------
__global__ void k_aggr(const int* __restrict__ src,
                       const int* __restrict__ dst) {
    unsigned int gid = blockIdx.x * blockDim.x + threadIdx.x;
    int e = (int)(gid >> 3);
    if (e >= ET) return;
    int c = (int)(gid & 7u) * 4;
    int s, d;
    if (e < Ee) { s = __ldg(src + e); d = __ldg(dst + e); }
    else        { s = d = e - Ee; }
    float coef = __fdividef(g_w[e], g_s[d]);
    const float4 hv = *(const float4*)(g_h + s * Dd + c);
    float4 v = make_float4(hv.x * coef, hv.y * coef, hv.z * coef, hv.w * coef);
    float* p = g_acc + d * Dd + c;
    asm volatile("red.global.add.v4.f32 [%0], {%1,%2,%3,%4};"
                 :: "l"(p), "f"(v.x), "f"(v.y), "f"(v.z), "f"(v.w)
                 : "memory");
}

// ---------------------------------------------------------------------------
// K4: out = elu(acc + b)
// ---------------------------------------------------------------------------
__global__ void k_bias_elu(const float* __restrict__ b,
                           float* __restrict__ out) {
    int i = blockIdx.x * blockDim.x + threadIdx.x;
    if (i >= Nn * Dd) return;
    float v = g_acc[i] + b[i & (Dd - 1)];
    out[i] = v > 0.f ? v : expm1f(v);
}

// ---------------------------------------------------------------------------
extern "C" void kernel_launch(void* const* d_in, const int* in_sizes, int n_in,
                              void* d_out, int out_size) {
    const float* x    = (const float*)d_in[0];
    const int*   ei   = (const int*)d_in[1];
    const int*   srcp = ei;
    const int*   dstp = ei + Ee;
    const float* W1   = (const float*)d_in[2];
    const float* as1  = (const float*)d_in[3];
    const float* ad1  = (const float*)d_in[4];
    const float* b1   = (const float*)d_in[5];
    const float* W2   = (const float*)d_in[6];
    const float* as2  = (const float*)d_in[7];
    const float* ad2  = (const float*)d_in[8];
    const float* b2   = (const float*)d_in[9];

    float* xbar = (float*)d_out;            // first N*D: xbar
    float* z    = (float*)d_out + Nn * Dd;  // second N*D: z

    const int TPB = 256;
    const int gGemm = (Nn + 7) / 8;                 // 8 warps/block, 1 row/warp
    const int gEdge = (ET + TPB - 1) / TPB;
    const int gAggr = (int)(((long long)ET * 8 + TPB - 1) / TPB);
    const int gElt  = (Nn * Dd + TPB - 1) / TPB;

    // ---- Layer 1 ----
    k_gemm_alpha<<<gGemm, TPB>>>(x, W1, as1, ad1);
    k_edge_w<<<gEdge, TPB>>>(srcp, dstp);
    k_aggr<<<gAggr, TPB>>>(srcp, dstp);
    k_bias_elu<<<gElt, TPB>>>(b1, z);

    // ---- Layer 2 (input z) ----
    k_gemm_alpha<<<gGemm, TPB>>>(z, W2, as2, ad2);
    k_edge_w<<<gEdge, TPB>>>(srcp, dstp);
    k_aggr<<<gAggr, TPB>>>(srcp, dstp);
    k_bias_elu<<<gElt, TPB>>>(b2, xbar);
}

// round 3
// speedup vs baseline: 1.1855x; 1.1855x over previous
#include <cuda_runtime.h>
#include <cuda_bf16.h>

#define Nn 100000
#define Ee 1600000
#define Dd 32
#define ET (Ee + Nn)                 // edges + self loops
#define NCHUNK ((Nn + 255) / 256)    // 391 scan chunks

// ---------------- device scratch (no allocations allowed) ----------------
__device__ float g_h[Nn * Dd];       // transformed features h = in @ W
__device__ float g_as[Nn];           // alpha_src per node
__device__ float g_ad[Nn];           // alpha_dst per node
__device__ int   g_cnt[Nn];          // in-degree (incl. self loop)
__device__ int   g_row[Nn];          // CSR row start (exclusive scan of cnt)
__device__ int   g_cur[Nn];          // scatter cursor
__device__ int   g_bsum[NCHUNK];     // scan block sums
__device__ int   g_sorted[ET];       // src indices sorted by dst

// ---------------------------------------------------------------------------
// CSR build: counting sort of edges by destination.
// ---------------------------------------------------------------------------
__global__ void k_init() {
    int i = blockIdx.x * blockDim.x + threadIdx.x;
    if (i < Nn) g_cnt[i] = 1;                      // self loop pre-counted
}

__global__ void k_hist(const int* __restrict__ dst) {
    int e = blockIdx.x * blockDim.x + threadIdx.x;
    if (e < Ee) atomicAdd(&g_cnt[dst[e]], 1);
}

__global__ void k_scanA() {                        // per-chunk exclusive scan
    __shared__ int sm[256];
    int i = blockIdx.x * 256 + threadIdx.x;
    int v = (i < Nn) ? g_cnt[i] : 0;
    sm[threadIdx.x] = v;
    __syncthreads();
    for (int o = 1; o < 256; o <<= 1) {
        int t = (threadIdx.x >= (unsigned)o) ? sm[threadIdx.x - o] : 0;
        __syncthreads();
        sm[threadIdx.x] += t;
        __syncthreads();
    }
    if (i < Nn) g_row[i] = sm[threadIdx.x] - v;    // exclusive
    if (threadIdx.x == 255) g_bsum[blockIdx.x] = sm[255];
}

__global__ void k_scanB() {                        // scan the 391 chunk totals
    __shared__ int sm[512];
    int t = threadIdx.x;
    int v = (t < NCHUNK) ? g_bsum[t] : 0;
    sm[t] = v;
    __syncthreads();
    for (int o = 1; o < 512; o <<= 1) {
        int x = (t >= o) ? sm[t - o] : 0;
        __syncthreads();
        sm[t] += x;
        __syncthreads();
    }
    if (t < NCHUNK) g_bsum[t] = sm[t] - v;         // exclusive
}

__global__ void k_scanC() {                        // add chunk offsets
    int i = blockIdx.x * blockDim.x + threadIdx.x;
    if (i >= Nn) return;
    int v = g_row[i] + g_bsum[i >> 8];
    g_row[i] = v;
    g_cur[i] = v;
}

__global__ void k_scatter(const int* __restrict__ src,
                          const int* __restrict__ dst) {
    int e = blockIdx.x * blockDim.x + threadIdx.x;
    if (e >= ET) return;
    int s, d;
    if (e < Ee) { s = src[e]; d = dst[e]; }
    else        { s = d = e - Ee; }                // self loop
    int pos = atomicAdd(&g_cur[d], 1);
    g_sorted[pos] = s;
}

// ---------------------------------------------------------------------------
// GEMM + alpha: h = in @ W (N x 32 @ 32 x 32), per-node dot products with
// a_src / a_dst. One warp per row.
// ---------------------------------------------------------------------------
__global__ void k_gemm_alpha(const float* __restrict__ in,
                             const float* __restrict__ W,
                             const float* __restrict__ a_s,
                             const float* __restrict__ a_d) {
    __shared__ float Ws[Dd * Dd];
    __shared__ float asv[Dd];
    __shared__ float adv[Dd];
    int tid = threadIdx.x;
    for (int i = tid; i < Dd * Dd; i += blockDim.x) Ws[i] = W[i];
    if (tid < Dd) { asv[tid] = a_s[tid]; adv[tid] = a_d[tid]; }
    __syncthreads();

    int warp = tid >> 5;
    int lane = tid & 31;
    int row = blockIdx.x * (blockDim.x >> 5) + warp;
    if (row >= Nn) return;

    float xr = in[row * Dd + lane];
    float h = 0.f;
#pragma unroll
    for (int k = 0; k < Dd; k++)
        h = fmaf(__shfl_sync(0xffffffffu, xr, k), Ws[k * Dd + lane], h);

    g_h[row * Dd + lane] = h;

    float vs = h * asv[lane];
    float vd = h * adv[lane];
#pragma unroll
    for (int o = 16; o > 0; o >>= 1) {
        vs += __shfl_xor_sync(0xffffffffu, vs, o);
        vd += __shfl_xor_sync(0xffffffffu, vd, o);
    }
    if (lane == 0) {
        g_as[row] = vs;
        g_ad[row] = vd;
    }
}

// ---------------------------------------------------------------------------
// Fused per-node GAT aggregation (softmax + weighted sum + bias + ELU).
// One warp per destination node; lane = feature column.
// Softmax max-subtraction omitted (shift-invariant; alpha is O(10) bounded).
// Division deferred: acc = sum(w * h[src]), out = elu(acc / sum(w) + b).
// ---------------------------------------------------------------------------
__global__ void k_node(const float* __restrict__ bias,
                       float* __restrict__ out) {
    int gw = (blockIdx.x * blockDim.x + threadIdx.x) >> 5;
    int lane = threadIdx.x & 31;
    if (gw >= Nn) return;

    int start = g_row[gw];
    int deg   = g_cnt[gw];
    float adv = g_ad[gw];

    float accv[4] = {0.f, 0.f, 0.f, 0.f};
    float wsum = 0.f;

    for (int k0 = 0; k0 < deg; k0 += 32) {
        int idx = k0 + lane;
        int s = 0;
        float w = 0.f;
        if (idx < deg) {
            s = g_sorted[start + idx];
            float a = g_as[s] + adv;
            a = a > 0.f ? a : 0.2f * a;            // leaky_relu(0.2)
            w = __expf(a);
        }
        wsum += w;
        int nb = deg - k0;                         // uniform across warp
#pragma unroll
        for (int j = 0; j < 32; j += 8) {
            if (j >= nb) break;                    // uniform branch
#pragma unroll
            for (int u = 0; u < 8; u++) {
                int   sj = __shfl_sync(0xffffffffu, s, j + u);
                float wj = __shfl_sync(0xffffffffu, w, j + u);
                // padded lanes: wj == 0 -> contributes exactly 0
                float hv = g_h[sj * Dd + lane];
                accv[u & 3] = fmaf(wj, hv, accv[u & 3]);
            }
        }
    }

    float acc = (accv[0] + accv[1]) + (accv[2] + accv[3]);
#pragma unroll
    for (int o = 16; o > 0; o >>= 1)
        wsum += __shfl_xor_sync(0xffffffffu, wsum, o);

    float v = __fdividef(acc, wsum) + bias[lane];
    out[gw * Dd + lane] = v > 0.f ? v : expm1f(v);
}

// ---------------------------------------------------------------------------
extern "C" void kernel_launch(void* const* d_in, const int* in_sizes, int n_in,
                              void* d_out, int out_size) {
    const float* x    = (const float*)d_in[0];
    const int*   ei   = (const int*)d_in[1];
    const int*   srcp = ei;
    const int*   dstp = ei + Ee;
    const float* W1   = (const float*)d_in[2];
    const float* as1  = (const float*)d_in[3];
    const float* ad1  = (const float*)d_in[4];
    const float* b1   = (const float*)d_in[5];
    const float* W2   = (const float*)d_in[6];
    const float* as2  = (const float*)d_in[7];
    const float* ad2  = (const float*)d_in[8];
    const float* b2   = (const float*)d_in[9];

    float* xbar = (float*)d_out;            // first N*D: xbar
    float* z    = (float*)d_out + Nn * Dd;  // second N*D: z

    const int TPB = 256;

    // ---- CSR build (shared by both layers) ----
    k_init   <<<(Nn + TPB - 1) / TPB, TPB>>>();
    k_hist   <<<(Ee + TPB - 1) / TPB, TPB>>>(dstp);
    k_scanA  <<<NCHUNK, 256>>>();
    k_scanB  <<<1, 512>>>();
    k_scanC  <<<(Nn + TPB - 1) / TPB, TPB>>>();
    k_scatter<<<(ET + TPB - 1) / TPB, TPB>>>(srcp, dstp);

    const int gGemm = (Nn + 7) / 8;         // 8 warps/block, 1 row/warp
    const int gNode = (Nn + 7) / 8;         // 8 warps/block, 1 node/warp

    // ---- Layer 1 ----
    k_gemm_alpha<<<gGemm, TPB>>>(x, W1, as1, ad1);
    k_node      <<<gNode, TPB>>>(b1, z);

    // ---- Layer 2 ----
    k_gemm_alpha<<<gGemm, TPB>>>(z, W2, as2, ad2);
    k_node      <<<gNode, TPB>>>(b2, xbar);
}